// round 2
// baseline (speedup 1.0000x reference)
#include <cuda_runtime.h>

#define BATCH 2048
#define SEQT  512
#define D_IN  32
#define HID   64
#define NG    256   // 4*H
#define NB    16    // batch rows per CTA
#define NT    256   // threads per CTA (one per gate row)

typedef unsigned long long u64;

// Scratch for layer-0 hidden sequence: [B, T, H] fp32 = 256 MB (bss, no alloc)
__device__ float g_h1[(size_t)BATCH * SEQT * HID];

__device__ __forceinline__ u64 ffma2(u64 a, u64 b, u64 c) {
    u64 d;
    asm("fma.rn.f32x2 %0, %1, %2, %3;" : "=l"(d) : "l"(a), "l"(b), "l"(c));
    return d;
}
__device__ __forceinline__ float u64lo(u64 v) { return __uint_as_float((unsigned)v); }
__device__ __forceinline__ float u64hi(u64 v) { return __uint_as_float((unsigned)(v >> 32)); }

__device__ __forceinline__ float sigmoid_f(float x) { return 1.0f / (1.0f + __expf(-x)); }
__device__ __forceinline__ float tanh_f(float x)    { return 2.0f / (1.0f + __expf(-2.0f * x)) - 1.0f; }

// One LSTM layer, persistent over T for a batch tile of NB rows.
// FIRST=true : input = xin [B,T,DIN], writes full h sequence to g_h1
// FIRST=false: input = g_h1 [B,T,HID], at the end computes LayerNorm+FC -> out[B]
template<int DIN, bool FIRST>
__global__ void __launch_bounds__(NT, 1)
lstm_layer_kernel(const float* __restrict__ xin,
                  const float* __restrict__ W_ih, const float* __restrict__ W_hh,
                  const float* __restrict__ b_ih, const float* __restrict__ b_hh,
                  const float* __restrict__ ln_g, const float* __restrict__ ln_b,
                  const float* __restrict__ fc_w, const float* __restrict__ fc_b,
                  float* __restrict__ out)
{
    __shared__ __align__(16) float sh_x[NB * DIN];   // current-step inputs
    __shared__ __align__(16) float sh_h[NB * HID];   // current hidden state
    __shared__ __align__(16) float sh_g[NB * NG];    // activated gates

    const int tid = threadIdx.x;          // gate row g in [0,256)
    const int b0  = blockIdx.x * NB;

    const float* xsrc = FIRST ? xin : (const float*)g_h1;

    // --- weights into registers as packed f32x2 pairs ---
    u64 wih[DIN / 2];
    {
        const u64* p = (const u64*)(W_ih + (size_t)tid * DIN);
        #pragma unroll
        for (int i = 0; i < DIN / 2; i++) wih[i] = p[i];
    }
    u64 whh[HID / 2];
    {
        const u64* p = (const u64*)(W_hh + (size_t)tid * HID);
        #pragma unroll
        for (int i = 0; i < HID / 2; i++) whh[i] = p[i];
    }
    const float bias = b_ih[tid] + b_hh[tid];
    const bool gate_tanh = ((tid >> 6) == 2);   // rows [128,192) are the g-gate

    // c-state in registers of the update threads (fixed (b,j) per thread per r)
    float creg[(NB * HID) / NT];   // = 4
    #pragma unroll
    for (int r = 0; r < (NB * HID) / NT; r++) creg[r] = 0.0f;
    for (int i = tid; i < NB * HID; i += NT) sh_h[i] = 0.0f;

    // --- preload x(t=0) ---
    constexpr int XQ  = DIN / 4;       // float4 per batch row
    constexpr int XLD = NB * XQ;       // total float4 loads per step
    const int xb = tid / XQ, xq = tid % XQ;
    float4 xpre;
    if (tid < XLD) {
        xpre = *(const float4*)(xsrc + ((size_t)(b0 + xb) * SEQT + 0) * DIN + xq * 4);
        *(float4*)(sh_x + xb * DIN + xq * 4) = xpre;
    }
    __syncthreads();

    for (int t = 0; t < SEQT; t++) {
        // prefetch next-step input into registers (consumed after barrier)
        if (t + 1 < SEQT && tid < XLD)
            xpre = *(const float4*)(xsrc + ((size_t)(b0 + xb) * SEQT + (t + 1)) * DIN + xq * 4);

        const ulonglong2* x2 = (const ulonglong2*)sh_x;   // 4 floats per element
        const ulonglong2* h2 = (const ulonglong2*)sh_h;

        // --- phase 1: gates = act( W_ih @ x + W_hh @ h + bias ) ---
        #pragma unroll 1
        for (int bb = 0; bb < NB; bb += 4) {
            u64 a0 = 0ull, a1 = 0ull, a2 = 0ull, a3 = 0ull;
            #pragma unroll
            for (int k = 0; k < DIN / 4; k++) {
                ulonglong2 v0 = x2[(bb + 0) * (DIN / 4) + k];
                ulonglong2 v1 = x2[(bb + 1) * (DIN / 4) + k];
                ulonglong2 v2 = x2[(bb + 2) * (DIN / 4) + k];
                ulonglong2 v3 = x2[(bb + 3) * (DIN / 4) + k];
                u64 wA = wih[2 * k], wB = wih[2 * k + 1];
                a0 = ffma2(wA, v0.x, a0); a0 = ffma2(wB, v0.y, a0);
                a1 = ffma2(wA, v1.x, a1); a1 = ffma2(wB, v1.y, a1);
                a2 = ffma2(wA, v2.x, a2); a2 = ffma2(wB, v2.y, a2);
                a3 = ffma2(wA, v3.x, a3); a3 = ffma2(wB, v3.y, a3);
            }
            #pragma unroll
            for (int k = 0; k < HID / 4; k++) {
                ulonglong2 v0 = h2[(bb + 0) * (HID / 4) + k];
                ulonglong2 v1 = h2[(bb + 1) * (HID / 4) + k];
                ulonglong2 v2 = h2[(bb + 2) * (HID / 4) + k];
                ulonglong2 v3 = h2[(bb + 3) * (HID / 4) + k];
                u64 wA = whh[2 * k], wB = whh[2 * k + 1];
                a0 = ffma2(wA, v0.x, a0); a0 = ffma2(wB, v0.y, a0);
                a1 = ffma2(wA, v1.x, a1); a1 = ffma2(wB, v1.y, a1);
                a2 = ffma2(wA, v2.x, a2); a2 = ffma2(wB, v2.y, a2);
                a3 = ffma2(wA, v3.x, a3); a3 = ffma2(wB, v3.y, a3);
            }
            float v;
            v = u64lo(a0) + u64hi(a0) + bias;
            sh_g[(bb + 0) * NG + tid] = gate_tanh ? tanh_f(v) : sigmoid_f(v);
            v = u64lo(a1) + u64hi(a1) + bias;
            sh_g[(bb + 1) * NG + tid] = gate_tanh ? tanh_f(v) : sigmoid_f(v);
            v = u64lo(a2) + u64hi(a2) + bias;
            sh_g[(bb + 2) * NG + tid] = gate_tanh ? tanh_f(v) : sigmoid_f(v);
            v = u64lo(a3) + u64hi(a3) + bias;
            sh_g[(bb + 3) * NG + tid] = gate_tanh ? tanh_f(v) : sigmoid_f(v);
        }
        __syncthreads();

        // --- phase 2: c/h update ---
        #pragma unroll
        for (int r = 0; r < (NB * HID) / NT; r++) {
            int e = tid + r * NT;
            int b = e >> 6, j = e & 63;
            float ig = sh_g[b * NG + j];
            float fg = sh_g[b * NG + 64 + j];
            float gg = sh_g[b * NG + 128 + j];
            float og = sh_g[b * NG + 192 + j];
            float c = fg * creg[r] + ig * gg;
            creg[r] = c;
            float h = og * tanh_f(c);
            sh_h[e] = h;
            if (FIRST)
                g_h1[((size_t)(b0 + b) * SEQT + t) * HID + j] = h;
        }
        // commit prefetched x(t+1)
        if (t + 1 < SEQT && tid < XLD)
            *(float4*)(sh_x + xb * DIN + xq * 4) = xpre;
        __syncthreads();
    }

    // --- fused LayerNorm + FC on last hidden state (layer 1 only) ---
    if (!FIRST) {
        if (tid < NB) {
            const float* h = sh_h + tid * HID;
            float mu = 0.0f;
            #pragma unroll
            for (int j = 0; j < HID; j++) mu += h[j];
            mu *= (1.0f / HID);
            float var = 0.0f;
            #pragma unroll
            for (int j = 0; j < HID; j++) { float d = h[j] - mu; var += d * d; }
            var *= (1.0f / HID);
            float rstd = rsqrtf(var + 1e-5f);
            float s = 0.0f;
            #pragma unroll
            for (int j = 0; j < HID; j++)
                s += ((h[j] - mu) * rstd * ln_g[j] + ln_b[j]) * fc_w[j];
            out[b0 + tid] = s + fc_b[0];
        }
    }
}

extern "C" void kernel_launch(void* const* d_in, const int* in_sizes, int n_in,
                              void* d_out, int out_size)
{
    const float* x     = (const float*)d_in[0];
    const float* W_ih0 = (const float*)d_in[1];
    const float* W_hh0 = (const float*)d_in[2];
    const float* b_ih0 = (const float*)d_in[3];
    const float* b_hh0 = (const float*)d_in[4];
    const float* W_ih1 = (const float*)d_in[5];
    const float* W_hh1 = (const float*)d_in[6];
    const float* b_ih1 = (const float*)d_in[7];
    const float* b_hh1 = (const float*)d_in[8];
    const float* ln_g  = (const float*)d_in[9];
    const float* ln_b  = (const float*)d_in[10];
    const float* fc_w  = (const float*)d_in[11];
    const float* fc_b  = (const float*)d_in[12];
    float* out = (float*)d_out;

    dim3 grid(BATCH / NB), block(NT);
    lstm_layer_kernel<D_IN, true ><<<grid, block>>>(x, W_ih0, W_hh0, b_ih0, b_hh0,
                                                    nullptr, nullptr, nullptr, nullptr, nullptr);
    lstm_layer_kernel<HID,  false><<<grid, block>>>(nullptr, W_ih1, W_hh1, b_ih1, b_hh1,
                                                    ln_g, ln_b, fc_w, fc_b, out);
}

// round 4
// speedup vs baseline: 1.9431x; 1.9431x over previous
#include <cuda_runtime.h>
#include <cuda_bf16.h>
#include <stdint.h>

#define SEQT    512
#define NB      16
#define NT      256
#define BSTRIDE 136    // halves per batch row in B (activation) buffers
#define GSTRIDE 260    // floats per batch row in gate-exchange buffer

// layer0 -> layer1 hidden sequence, bf16 hi|lo packed in u32: [b][t][j]
__device__ uint32_t g_h1[(size_t)2048 * SEQT * 64];

__device__ __forceinline__ void mma_bf16(float c[4],
                                         const uint32_t a[4],
                                         uint32_t b0, uint32_t b1) {
    asm volatile(
        "mma.sync.aligned.m16n8k16.row.col.f32.bf16.bf16.f32 "
        "{%0,%1,%2,%3}, {%4,%5,%6,%7}, {%8,%9}, {%0,%1,%2,%3};"
        : "+f"(c[0]), "+f"(c[1]), "+f"(c[2]), "+f"(c[3])
        : "r"(a[0]), "r"(a[1]), "r"(a[2]), "r"(a[3]), "r"(b0), "r"(b1));
}

__device__ __forceinline__ void split_bf16(float v, uint16_t& hi, uint16_t& lo) {
    __nv_bfloat16 h = __float2bfloat16(v);
    __nv_bfloat16 l = __float2bfloat16(v - __bfloat162float(h));
    hi = __bfloat16_as_ushort(h);
    lo = __bfloat16_as_ushort(l);
}

__device__ __forceinline__ float sigmoid_f(float x) { return 1.0f / (1.0f + __expf(-x)); }
__device__ __forceinline__ float tanh_f(float x)    { return 2.0f / (1.0f + __expf(-2.0f * x)) - 1.0f; }

// One recurrent LSTM layer, persistent over T.
// FIRST: input = x [2048,512,32] fused in K (K=96), writes h to g_h1.
// !FIRST: input = g_h1 (K=128), ends with LayerNorm+FC.
template<int KT, bool FIRST>
__global__ void __launch_bounds__(NT, 1)
lstm_rec(const float* __restrict__ x,
         const float* __restrict__ W_ih,   // [256, DIN]
         const float* __restrict__ W_hh,   // [256, 64]
         const float* __restrict__ b_ih, const float* __restrict__ b_hh,
         const float* __restrict__ ln_g, const float* __restrict__ ln_b,
         const float* __restrict__ fc_w, const float* __restrict__ fc_b,
         float* __restrict__ out)
{
    constexpr int DIN  = FIRST ? 32 : 64;   // leading K region (non-recurrent input)
    constexpr int HOFF = DIN;               // k offset of recurrent h

    __shared__ __align__(16) uint16_t sBhi[NB][BSTRIDE];
    __shared__ __align__(16) uint16_t sBlo[NB][BSTRIDE];
    __shared__ __align__(16) float    sG[NB][GSTRIDE];

    const int tid  = threadIdx.x;
    const int w    = tid >> 5;
    const int lane = tid & 31;
    const int g    = lane >> 2;     // fragment row/col group
    const int tq   = lane & 3;      // fragment pair index
    const int b0   = blockIdx.x * NB;

    // ---- A fragments (weights) in registers, bf16 hi/lo ----
    uint32_t Ahi[2][KT][4], Alo[2][KT][4];
    float bias[2][2];
    #pragma unroll
    for (int mt = 0; mt < 2; mt++) {
        #pragma unroll
        for (int kt = 0; kt < KT; kt++) {
            #pragma unroll
            for (int i = 0; i < 4; i++) {
                int m = 32 * w + 16 * mt + g + (i & 1) * 8;
                int k = 16 * kt + 2 * tq + (i >> 1) * 8;
                float v0 = (k < DIN)     ? W_ih[m * DIN + k]     : W_hh[m * 64 + (k - DIN)];
                float v1 = (k + 1 < DIN) ? W_ih[m * DIN + k + 1] : W_hh[m * 64 + (k + 1 - DIN)];
                uint16_t h0, l0, h1, l1;
                split_bf16(v0, h0, l0);
                split_bf16(v1, h1, l1);
                Ahi[mt][kt][i] = (uint32_t)h0 | ((uint32_t)h1 << 16);
                Alo[mt][kt][i] = (uint32_t)l0 | ((uint32_t)l1 << 16);
            }
        }
        #pragma unroll
        for (int r = 0; r < 2; r++) {
            int m = 32 * w + 16 * mt + g + 8 * r;
            bias[mt][r] = b_ih[m] + b_hh[m];
        }
    }

    // zero B buffers (h region starts at 0)
    for (int i = tid; i < NB * BSTRIDE; i += NT) {
        ((uint16_t*)sBhi)[i] = 0;
        ((uint16_t*)sBlo)[i] = 0;
    }

    // input(t=0) into B
    if (FIRST) {
        int b = tid >> 4, kx = (tid & 15) * 2;
        float2 xv = *(const float2*)(x + ((size_t)(b0 + b) * SEQT + 0) * 32 + kx);
        uint16_t h0, l0, h1, l1;
        split_bf16(xv.x, h0, l0);
        split_bf16(xv.y, h1, l1);
        sBhi[b][kx] = h0; sBhi[b][kx + 1] = h1;
        sBlo[b][kx] = l0; sBlo[b][kx + 1] = l1;
    } else {
        #pragma unroll
        for (int q = 0; q < 4; q++) {
            int s = tid + 256 * q, b = s >> 6, kh = s & 63;
            uint32_t v = g_h1[((size_t)(b0 + b) * SEQT + 0) * 64 + kh];
            sBhi[b][kh] = (uint16_t)v;
            sBlo[b][kh] = (uint16_t)(v >> 16);
        }
    }
    __syncthreads();

    float cst[4] = {0, 0, 0, 0};
    float hreg[4];
    const bool isg0 = ((32 * w + g) >> 6) == 2;        // gate type of row g (mt/r adjusted below)

    #pragma unroll 1
    for (int t = 0; t < SEQT; t++) {
        // ---- prefetch next input ----
        float2 nx;
        uint32_t nh[4];
        if (FIRST) {
            if (t + 1 < SEQT) {
                int b = tid >> 4, kx = (tid & 15) * 2;
                nx = *(const float2*)(x + ((size_t)(b0 + b) * SEQT + (t + 1)) * 32 + kx);
            }
        } else {
            if (t + 1 < SEQT) {
                #pragma unroll
                for (int q = 0; q < 4; q++) {
                    int s = tid + 256 * q, b = s >> 6, kh = s & 63;
                    nh[q] = g_h1[((size_t)(b0 + b) * SEQT + (t + 1)) * 64 + kh];
                }
            }
        }

        // ---- MMA: C[mt][nt] = W * B ----
        float C[2][2][4];
        #pragma unroll
        for (int mt = 0; mt < 2; mt++)
            #pragma unroll
            for (int nt = 0; nt < 2; nt++)
                #pragma unroll
                for (int i = 0; i < 4; i++) C[mt][nt][i] = 0.0f;

        #pragma unroll
        for (int kt = 0; kt < KT; kt++) {
            uint32_t bh[2][2], bl[2][2];
            #pragma unroll
            for (int nt = 0; nt < 2; nt++) {
                int n = 8 * nt + g;
                int k = 16 * kt + 2 * tq;
                bh[nt][0] = *(const uint32_t*)&sBhi[n][k];
                bh[nt][1] = *(const uint32_t*)&sBhi[n][k + 8];
                bl[nt][0] = *(const uint32_t*)&sBlo[n][k];
                bl[nt][1] = *(const uint32_t*)&sBlo[n][k + 8];
            }
            #pragma unroll
            for (int mt = 0; mt < 2; mt++)
                #pragma unroll
                for (int nt = 0; nt < 2; nt++) {
                    mma_bf16(C[mt][nt], Ahi[mt][kt], bh[nt][0], bh[nt][1]);
                    mma_bf16(C[mt][nt], Ahi[mt][kt], bl[nt][0], bl[nt][1]);
                    mma_bf16(C[mt][nt], Alo[mt][kt], bh[nt][0], bh[nt][1]);
                }
        }

        // ---- bias + activation -> gate exchange ----
        #pragma unroll
        for (int mt = 0; mt < 2; mt++) {
            #pragma unroll
            for (int r = 0; r < 2; r++) {
                int m = 32 * w + 16 * mt + g + 8 * r;
                bool is_tanh = ((m >> 6) == 2);
                #pragma unroll
                for (int nt = 0; nt < 2; nt++) {
                    int n = 8 * nt + 2 * tq;
                    float v0 = C[mt][nt][2 * r]     + bias[mt][r];
                    float v1 = C[mt][nt][2 * r + 1] + bias[mt][r];
                    sG[n][m]     = is_tanh ? tanh_f(v0) : sigmoid_f(v0);
                    sG[n + 1][m] = is_tanh ? tanh_f(v1) : sigmoid_f(v1);
                }
            }
        }
        __syncthreads();

        // ---- c/h update (fixed cell ownership) ----
        #pragma unroll
        for (int r = 0; r < 4; r++) {
            int e = tid + 256 * r, b = e >> 6, j = e & 63;
            float ig = sG[b][j];
            float fg = sG[b][64 + j];
            float gg = sG[b][128 + j];
            float og = sG[b][192 + j];
            float c = fg * cst[r] + ig * gg;
            cst[r] = c;
            float h = og * tanh_f(c);
            hreg[r] = h;
            uint16_t hh, hl;
            split_bf16(h, hh, hl);
            sBhi[b][HOFF + j] = hh;
            sBlo[b][HOFF + j] = hl;
            if (FIRST)
                g_h1[((size_t)(b0 + b) * SEQT + t) * 64 + j] =
                    (uint32_t)hh | ((uint32_t)hl << 16);
        }

        // ---- commit prefetched input ----
        if (FIRST) {
            if (t + 1 < SEQT) {
                int b = tid >> 4, kx = (tid & 15) * 2;
                uint16_t h0, l0, h1, l1;
                split_bf16(nx.x, h0, l0);
                split_bf16(nx.y, h1, l1);
                sBhi[b][kx] = h0; sBhi[b][kx + 1] = h1;
                sBlo[b][kx] = l0; sBlo[b][kx + 1] = l1;
            }
        } else {
            if (t + 1 < SEQT) {
                #pragma unroll
                for (int q = 0; q < 4; q++) {
                    int s = tid + 256 * q, b = s >> 6, kh = s & 63;
                    sBhi[b][kh] = (uint16_t)nh[q];
                    sBlo[b][kh] = (uint16_t)(nh[q] >> 16);
                }
            }
        }
        __syncthreads();
    }

    (void)isg0;

    // ---- LayerNorm + FC (layer 1 only) ----
    if (!FIRST) {
        #pragma unroll
        for (int r = 0; r < 4; r++) {
            int e = tid + 256 * r, b = e >> 6, j = e & 63;
            sG[b][j] = hreg[r];
        }
        __syncthreads();
        if (tid < NB) {
            const float* h = sG[tid];
            float mu = 0.0f;
            #pragma unroll
            for (int j = 0; j < 64; j++) mu += h[j];
            mu *= (1.0f / 64.0f);
            float var = 0.0f;
            #pragma unroll
            for (int j = 0; j < 64; j++) { float d = h[j] - mu; var += d * d; }
            var *= (1.0f / 64.0f);
            float rstd = rsqrtf(var + 1e-5f);
            float s = 0.0f;
            #pragma unroll
            for (int j = 0; j < 64; j++)
                s += ((h[j] - mu) * rstd * ln_g[j] + ln_b[j]) * fc_w[j];
            out[b0 + tid] = s + fc_b[0];
        }
    }
}

extern "C" void kernel_launch(void* const* d_in, const int* in_sizes, int n_in,
                              void* d_out, int out_size)
{
    const float* x     = (const float*)d_in[0];
    const float* W_ih0 = (const float*)d_in[1];
    const float* W_hh0 = (const float*)d_in[2];
    const float* b_ih0 = (const float*)d_in[3];
    const float* b_hh0 = (const float*)d_in[4];
    const float* W_ih1 = (const float*)d_in[5];
    const float* W_hh1 = (const float*)d_in[6];
    const float* b_ih1 = (const float*)d_in[7];
    const float* b_hh1 = (const float*)d_in[8];
    const float* ln_g  = (const float*)d_in[9];
    const float* ln_b  = (const float*)d_in[10];
    const float* fc_w  = (const float*)d_in[11];
    const float* fc_b  = (const float*)d_in[12];
    float* out = (float*)d_out;

    lstm_rec<6, true ><<<2048 / NB, NT>>>(x, W_ih0, W_hh0, b_ih0, b_hh0,
                                          nullptr, nullptr, nullptr, nullptr, nullptr);
    lstm_rec<8, false><<<2048 / NB, NT>>>(nullptr, W_ih1, W_hh1, b_ih1, b_hh1,
                                          ln_g, ln_b, fc_w, fc_b, out);
}

// round 5
// speedup vs baseline: 3.2452x; 1.6701x over previous
#include <cuda_runtime.h>
#include <cuda_bf16.h>
#include <stdint.h>

#define SEQT 512
#define NB   16
#define NT   512
#define NW   16

// B-activation buffer strides (bytes per batch row); hi/lo interleaved 16B groups
#define S0   448    // layer0 K=96: 6 groups*64B, padded so (S/16)%8==4 -> conflict-free uint4
#define S1   576    // layer1 K=128: 8*64B, padded likewise
#define SGr  260    // gate exchange row stride in floats ((2*SGr)%32==8 -> conflict-free stores)

// dynamic SMEM offsets (bytes)
#define OFF_B0   0
#define OFF_B1   (OFF_B0 + NB * S0)                    // 7168
#define OFF_G0   (OFF_B1 + NB * S1)                    // 16384
#define OFF_G1   (OFF_G0 + NB * SGr * 4)               // 33024
#define OFF_ALO  (OFF_G1 + NB * SGr * 4)               // 49664
#define ALO_W    (14 * 32 * 16)                        // 7168 B per warp (14 kt-slots)
#define SMEM_TOTAL (OFF_ALO + NW * ALO_W)              // 164352

__device__ __forceinline__ void mma_bf16(float c[4], const uint32_t a[4],
                                         uint32_t b0, uint32_t b1) {
    asm volatile(
        "mma.sync.aligned.m16n8k16.row.col.f32.bf16.bf16.f32 "
        "{%0,%1,%2,%3}, {%4,%5,%6,%7}, {%8,%9}, {%0,%1,%2,%3};"
        : "+f"(c[0]), "+f"(c[1]), "+f"(c[2]), "+f"(c[3])
        : "r"(a[0]), "r"(a[1]), "r"(a[2]), "r"(a[3]), "r"(b0), "r"(b1));
}

__device__ __forceinline__ void split_bf16(float v, uint16_t& hi, uint16_t& lo) {
    __nv_bfloat16 h = __float2bfloat16(v);
    __nv_bfloat16 l = __float2bfloat16(v - __bfloat162float(h));
    hi = __bfloat16_as_ushort(h);
    lo = __bfloat16_as_ushort(l);
}

__device__ __forceinline__ float ex2f(float v) { float r; asm("ex2.approx.f32 %0, %1;" : "=f"(r) : "f"(v)); return r; }
__device__ __forceinline__ float rcpf(float v) { float r; asm("rcp.approx.f32 %0, %1;" : "=f"(r) : "f"(v)); return r; }
__device__ __forceinline__ float sigf(float x)  { return rcpf(1.0f + ex2f(-1.442695041f * x)); }
__device__ __forceinline__ float tanhf_(float x){ return fmaf(2.0f, rcpf(1.0f + ex2f(-2.885390082f * x)), -1.0f); }

// byte offset of (batch n, k-index k) inside a hi/lo-interleaved B buffer
// group(n,kt,tq) is 16B: [hi k0,k1 | hi k8,k9 | lo k0,k1 | lo k8,k9]
__device__ __forceinline__ int boff(int n, int k, int S) {
    int r = k & 15;
    return n * S + (k >> 4) * 64 + ((r >> 1) & 3) * 16 + ((r >> 3) << 2) + ((r & 1) << 1);
}

__global__ void __launch_bounds__(NT, 1)
lstm_fused(const float* __restrict__ x,
           const float* __restrict__ W_ih0, const float* __restrict__ W_hh0,
           const float* __restrict__ b_ih0, const float* __restrict__ b_hh0,
           const float* __restrict__ W_ih1, const float* __restrict__ W_hh1,
           const float* __restrict__ b_ih1, const float* __restrict__ b_hh1,
           const float* __restrict__ ln_g, const float* __restrict__ ln_b,
           const float* __restrict__ fc_w, const float* __restrict__ fc_b,
           float* __restrict__ out)
{
    extern __shared__ __align__(16) unsigned char sm[];
    const int tid  = threadIdx.x;
    const int w    = tid >> 5;
    const int lane = tid & 31;
    const int g    = lane >> 2;
    const int tq   = lane & 3;
    const int b0   = blockIdx.x * NB;

    // zero activation buffers (h regions must start at 0)
    for (int i = tid; i < OFF_G0 / 4; i += NT) ((uint32_t*)sm)[i] = 0;

    // ---- A fragments: hi in registers, lo in per-warp SMEM ----
    uint32_t A0[6][4], A1[8][4];
    #pragma unroll
    for (int kt = 0; kt < 6; kt++) {
        uint32_t lo4[4];
        #pragma unroll
        for (int i = 0; i < 4; i++) {
            int m = 16 * w + g + (i & 1) * 8;
            int k = 16 * kt + 2 * tq + (i >> 1) * 8;
            float v0 = (k < 32)     ? W_ih0[m * 32 + k]     : W_hh0[m * 64 + k - 32];
            float v1 = (k + 1 < 32) ? W_ih0[m * 32 + k + 1] : W_hh0[m * 64 + k + 1 - 32];
            uint16_t h0, l0, h1, l1;
            split_bf16(v0, h0, l0); split_bf16(v1, h1, l1);
            A0[kt][i] = (uint32_t)h0 | ((uint32_t)h1 << 16);
            lo4[i]    = (uint32_t)l0 | ((uint32_t)l1 << 16);
        }
        *(uint4*)(sm + OFF_ALO + w * ALO_W + kt * 512 + lane * 16) = *(uint4*)lo4;
    }
    #pragma unroll
    for (int kt = 0; kt < 8; kt++) {
        uint32_t lo4[4];
        #pragma unroll
        for (int i = 0; i < 4; i++) {
            int m = 16 * w + g + (i & 1) * 8;
            int k = 16 * kt + 2 * tq + (i >> 1) * 8;
            float v0 = (k < 64)     ? W_ih1[m * 64 + k]     : W_hh1[m * 64 + k - 64];
            float v1 = (k + 1 < 64) ? W_ih1[m * 64 + k + 1] : W_hh1[m * 64 + k + 1 - 64];
            uint16_t h0, l0, h1, l1;
            split_bf16(v0, h0, l0); split_bf16(v1, h1, l1);
            A1[kt][i] = (uint32_t)h0 | ((uint32_t)h1 << 16);
            lo4[i]    = (uint32_t)l0 | ((uint32_t)l1 << 16);
        }
        *(uint4*)(sm + OFF_ALO + w * ALO_W + (6 + kt) * 512 + lane * 16) = *(uint4*)lo4;
    }

    float bias0[2], bias1[2];
    #pragma unroll
    for (int r = 0; r < 2; r++) {
        int m = 16 * w + g + 8 * r;
        bias0[r] = b_ih0[m] + b_hh0[m];
        bias1[r] = b_ih1[m] + b_hh1[m];
    }

    // x(t=0)
    const int xb = tid >> 5, xk = tid & 31;
    {
        float xv = x[((size_t)(b0 + xb) * SEQT + 0) * 32 + xk];
        uint16_t hh, hl; split_bf16(xv, hh, hl);
        int o = boff(xb, xk, S0);
        *(uint16_t*)(sm + OFF_B0 + o)     = hh;
        *(uint16_t*)(sm + OFF_B0 + o + 8) = hl;
    }
    __syncthreads();

    float* const gr0 = (float*)(sm + OFF_G0);
    float* const gr1 = (float*)(sm + OFF_G1);
    float c0s[2] = {0, 0}, c1s[2] = {0, 0}, h1fin[2] = {0, 0};

    #pragma unroll 1
    for (int p = 0; p <= SEQT; p++) {
        float xn = 0.0f;
        if (p + 1 < SEQT)
            xn = x[((size_t)(b0 + xb) * SEQT + (p + 1)) * 32 + xk];

        float C0[2][4] = {{0,0,0,0},{0,0,0,0}};
        float C1[2][4] = {{0,0,0,0},{0,0,0,0}};

        if (p < SEQT) {
            #pragma unroll
            for (int kt = 0; kt < 6; kt++) {
                uint4 al = *(const uint4*)(sm + OFF_ALO + w * ALO_W + kt * 512 + lane * 16);
                #pragma unroll
                for (int nt = 0; nt < 2; nt++) {
                    uint4 v = *(const uint4*)(sm + OFF_B0 + (8 * nt + g) * S0 + kt * 64 + tq * 16);
                    mma_bf16(C0[nt], A0[kt], v.x, v.y);          // Whi * Bhi
                    mma_bf16(C0[nt], A0[kt], v.z, v.w);          // Whi * Blo
                    mma_bf16(C0[nt], (const uint32_t*)&al, v.x, v.y); // Wlo * Bhi
                }
            }
        }
        if (p >= 1) {
            #pragma unroll
            for (int kt = 0; kt < 8; kt++) {
                uint4 al = *(const uint4*)(sm + OFF_ALO + w * ALO_W + (6 + kt) * 512 + lane * 16);
                #pragma unroll
                for (int nt = 0; nt < 2; nt++) {
                    uint4 v = *(const uint4*)(sm + OFF_B1 + (8 * nt + g) * S1 + kt * 64 + tq * 16);
                    mma_bf16(C1[nt], A1[kt], v.x, v.y);
                    mma_bf16(C1[nt], A1[kt], v.z, v.w);
                    mma_bf16(C1[nt], (const uint32_t*)&al, v.x, v.y);
                }
            }
        }

        // activations -> gate exchange
        if (p < SEQT) {
            #pragma unroll
            for (int r = 0; r < 2; r++) {
                int m = 16 * w + g + 8 * r;
                bool th = ((m >> 6) == 2);
                #pragma unroll
                for (int nt = 0; nt < 2; nt++)
                    #pragma unroll
                    for (int d = 0; d < 2; d++) {
                        float v = C0[nt][2 * r + d] + bias0[r];
                        gr0[(8 * nt + 2 * tq + d) * SGr + m] = th ? tanhf_(v) : sigf(v);
                    }
            }
        }
        if (p >= 1) {
            #pragma unroll
            for (int r = 0; r < 2; r++) {
                int m = 16 * w + g + 8 * r;
                bool th = ((m >> 6) == 2);
                #pragma unroll
                for (int nt = 0; nt < 2; nt++)
                    #pragma unroll
                    for (int d = 0; d < 2; d++) {
                        float v = C1[nt][2 * r + d] + bias1[r];
                        gr1[(8 * nt + 2 * tq + d) * SGr + m] = th ? tanhf_(v) : sigf(v);
                    }
            }
        }
        __syncthreads();

        // updates
        if (p < SEQT) {
            #pragma unroll
            for (int q = 0; q < 2; q++) {
                int e = tid + NT * q, b = e >> 6, j = e & 63;
                float ig = gr0[b * SGr + j];
                float fg = gr0[b * SGr + 64 + j];
                float gg = gr0[b * SGr + 128 + j];
                float og = gr0[b * SGr + 192 + j];
                float c = fg * c0s[q] + ig * gg;
                c0s[q] = c;
                float h = og * tanhf_(c);
                uint16_t hh, hl; split_bf16(h, hh, hl);
                int oa = boff(b, 32 + j, S0);
                *(uint16_t*)(sm + OFF_B0 + oa)     = hh;   // layer0 recurrence
                *(uint16_t*)(sm + OFF_B0 + oa + 8) = hl;
                int ob = boff(b, j, S1);
                *(uint16_t*)(sm + OFF_B1 + ob)     = hh;   // layer1 input
                *(uint16_t*)(sm + OFF_B1 + ob + 8) = hl;
            }
        }
        if (p >= 1) {
            #pragma unroll
            for (int q = 0; q < 2; q++) {
                int e = tid + NT * q, b = e >> 6, j = e & 63;
                float ig = gr1[b * SGr + j];
                float fg = gr1[b * SGr + 64 + j];
                float gg = gr1[b * SGr + 128 + j];
                float og = gr1[b * SGr + 192 + j];
                float c = fg * c1s[q] + ig * gg;
                c1s[q] = c;
                float h = og * tanhf_(c);
                h1fin[q] = h;
                uint16_t hh, hl; split_bf16(h, hh, hl);
                int oc = boff(b, 64 + j, S1);
                *(uint16_t*)(sm + OFF_B1 + oc)     = hh;   // layer1 recurrence
                *(uint16_t*)(sm + OFF_B1 + oc + 8) = hl;
            }
        }
        if (p + 1 < SEQT) {
            uint16_t hh, hl; split_bf16(xn, hh, hl);
            int o = boff(xb, xk, S0);
            *(uint16_t*)(sm + OFF_B0 + o)     = hh;
            *(uint16_t*)(sm + OFF_B0 + o + 8) = hl;
        }
        __syncthreads();
    }

    // ---- LayerNorm + FC on h1(T-1) ----
    #pragma unroll
    for (int q = 0; q < 2; q++) {
        int e = tid + NT * q;
        gr0[e] = h1fin[q];          // flat [b*64 + j]
    }
    __syncthreads();
    if (tid < NB) {
        const float* h = gr0 + tid * 64;
        float mu = 0.0f;
        #pragma unroll
        for (int j = 0; j < 64; j++) mu += h[j];
        mu *= (1.0f / 64.0f);
        float var = 0.0f;
        #pragma unroll
        for (int j = 0; j < 64; j++) { float d = h[j] - mu; var += d * d; }
        var *= (1.0f / 64.0f);
        float rstd = rsqrtf(var + 1e-5f);
        float s = 0.0f;
        #pragma unroll
        for (int j = 0; j < 64; j++)
            s += ((h[j] - mu) * rstd * ln_g[j] + ln_b[j]) * fc_w[j];
        out[b0 + tid] = s + fc_b[0];
    }
}

extern "C" void kernel_launch(void* const* d_in, const int* in_sizes, int n_in,
                              void* d_out, int out_size)
{
    const float* x     = (const float*)d_in[0];
    const float* W_ih0 = (const float*)d_in[1];
    const float* W_hh0 = (const float*)d_in[2];
    const float* b_ih0 = (const float*)d_in[3];
    const float* b_hh0 = (const float*)d_in[4];
    const float* W_ih1 = (const float*)d_in[5];
    const float* W_hh1 = (const float*)d_in[6];
    const float* b_ih1 = (const float*)d_in[7];
    const float* b_hh1 = (const float*)d_in[8];
    const float* ln_g  = (const float*)d_in[9];
    const float* ln_b  = (const float*)d_in[10];
    const float* fc_w  = (const float*)d_in[11];
    const float* fc_b  = (const float*)d_in[12];
    float* out = (float*)d_out;

    cudaFuncSetAttribute(lstm_fused, cudaFuncAttributeMaxDynamicSharedMemorySize, SMEM_TOTAL);
    lstm_fused<<<2048 / NB, NT, SMEM_TOTAL>>>(x, W_ih0, W_hh0, b_ih0, b_hh0,
                                              W_ih1, W_hh1, b_ih1, b_hh1,
                                              ln_g, ln_b, fc_w, fc_b, out);
}

// round 6
// speedup vs baseline: 3.4265x; 1.0559x over previous
#include <cuda_runtime.h>
#include <cuda_bf16.h>
#include <stdint.h>

#define SEQT 512
#define NB   16
#define NT   512

#define S0   448    // layer0 B row stride (K=96 -> 6x64B groups, padded)
#define S1   576    // layer1 B row stride (K=128 -> 8x64B groups, padded)

// dynamic SMEM map (bytes)
#define OFF_B0   0                         // 2 parities x 16*448 = 14336
#define OFF_B1   14336                     // 2 parities x 16*576 = 18432
#define OFF_X0   32768                     // L0 exchange: 16 slots x 512B = 8192
#define OFF_X1   40960                     // L1 exchange: 8192
#define OFF_ALO  49152                     // 16 warps x 7168
#define ALO_W    7168
#define SMEM_TOTAL (OFF_ALO + 16 * ALO_W)  // 163840

__device__ __forceinline__ void mma_bf16(float c[4], const uint32_t a[4],
                                         uint32_t b0, uint32_t b1) {
    asm volatile(
        "mma.sync.aligned.m16n8k16.row.col.f32.bf16.bf16.f32 "
        "{%0,%1,%2,%3}, {%4,%5,%6,%7}, {%8,%9}, {%0,%1,%2,%3};"
        : "+f"(c[0]), "+f"(c[1]), "+f"(c[2]), "+f"(c[3])
        : "r"(a[0]), "r"(a[1]), "r"(a[2]), "r"(a[3]), "r"(b0), "r"(b1));
}

__device__ __forceinline__ void split_bf16(float v, uint16_t& hi, uint16_t& lo) {
    __nv_bfloat16 h = __float2bfloat16(v);
    __nv_bfloat16 l = __float2bfloat16(v - __bfloat162float(h));
    hi = __bfloat16_as_ushort(h);
    lo = __bfloat16_as_ushort(l);
}

__device__ __forceinline__ float ex2f(float v) { float r; asm("ex2.approx.f32 %0, %1;" : "=f"(r) : "f"(v)); return r; }
__device__ __forceinline__ float rcpf(float v) { float r; asm("rcp.approx.f32 %0, %1;" : "=f"(r) : "f"(v)); return r; }
__device__ __forceinline__ float sigf(float x)   { return rcpf(1.0f + ex2f(-1.442695041f * x)); }
__device__ __forceinline__ float tanhf_(float x) { return fmaf(2.0f, rcpf(1.0f + ex2f(-2.885390082f * x)), -1.0f); }

// byte offset of (batch n, k) in hi/lo-interleaved B buffer
__device__ __forceinline__ int boff(int n, int k, int S) {
    int r = k & 15;
    return n * S + (k >> 4) * 64 + ((r >> 1) & 3) * 16 + ((r >> 3) << 2) + ((r & 1) << 1);
}

__global__ void __launch_bounds__(NT, 1)
lstm_fused(const float* __restrict__ x,
           const float* __restrict__ W_ih0, const float* __restrict__ W_hh0,
           const float* __restrict__ b_ih0, const float* __restrict__ b_hh0,
           const float* __restrict__ W_ih1, const float* __restrict__ W_hh1,
           const float* __restrict__ b_ih1, const float* __restrict__ b_hh1,
           const float* __restrict__ ln_g, const float* __restrict__ ln_b,
           const float* __restrict__ fc_w, const float* __restrict__ fc_b,
           float* __restrict__ out)
{
    extern __shared__ __align__(16) unsigned char sm[];
    const int tid  = threadIdx.x;
    const int w    = tid >> 5;
    const int lane = tid & 31;
    const int g    = lane >> 2;
    const int tq   = lane & 3;
    const int wp   = w & 7;          // j-block
    const int hi   = w >> 3;         // 0: gates {i,f}, 1: gates {g,o}
    const int jv   = 8 * wp + g;     // cell index this thread owns
    const int b0   = blockIdx.x * NB;

    // zero both parities of B0/B1 (h regions must start at 0)
    for (int i = tid; i < 32768 / 4; i += NT) ((uint32_t*)sm)[i] = 0;

    // ---- A fragments (reordered rows: gate pair per warp), hi regs / lo SMEM ----
    uint32_t A0[6][4], A1[8][4];
    #pragma unroll
    for (int kt = 0; kt < 6; kt++) {
        uint32_t lo4[4];
        #pragma unroll
        for (int i = 0; i < 4; i++) {
            int m = (2 * hi + (i & 1)) * 64 + jv;
            int k = 16 * kt + 2 * tq + (i >> 1) * 8;
            float v0 = (k < 32)     ? W_ih0[m * 32 + k]     : W_hh0[m * 64 + k - 32];
            float v1 = (k + 1 < 32) ? W_ih0[m * 32 + k + 1] : W_hh0[m * 64 + k + 1 - 32];
            uint16_t h0, l0, h1, l1;
            split_bf16(v0, h0, l0); split_bf16(v1, h1, l1);
            A0[kt][i] = (uint32_t)h0 | ((uint32_t)h1 << 16);
            lo4[i]    = (uint32_t)l0 | ((uint32_t)l1 << 16);
        }
        *(uint4*)(sm + OFF_ALO + w * ALO_W + kt * 512 + lane * 16) = *(uint4*)lo4;
    }
    #pragma unroll
    for (int kt = 0; kt < 8; kt++) {
        uint32_t lo4[4];
        #pragma unroll
        for (int i = 0; i < 4; i++) {
            int m = (2 * hi + (i & 1)) * 64 + jv;
            int k = 16 * kt + 2 * tq + (i >> 1) * 8;
            float v0 = (k < 64)     ? W_ih1[m * 64 + k]     : W_hh1[m * 64 + k - 64];
            float v1 = (k + 1 < 64) ? W_ih1[m * 64 + k + 1] : W_hh1[m * 64 + k + 1 - 64];
            uint16_t h0, l0, h1, l1;
            split_bf16(v0, h0, l0); split_bf16(v1, h1, l1);
            A1[kt][i] = (uint32_t)h0 | ((uint32_t)h1 << 16);
            lo4[i]    = (uint32_t)l0 | ((uint32_t)l1 << 16);
        }
        *(uint4*)(sm + OFF_ALO + w * ALO_W + (6 + kt) * 512 + lane * 16) = *(uint4*)lo4;
    }

    float bias0[2], bias1[2];
    #pragma unroll
    for (int r = 0; r < 2; r++) {
        int m = (2 * hi + r) * 64 + jv;
        bias0[r] = b_ih0[m] + b_hh0[m];
        bias1[r] = b_ih1[m] + b_hh1[m];
    }

    // x(0) -> B0 parity 0 (warp = batch row, lane = k)
    {
        float xv = x[((size_t)(b0 + w) * SEQT) * 32 + lane];
        uint16_t hh, hl; split_bf16(xv, hh, hl);
        int o = boff(w, lane, S0);
        *(uint16_t*)(sm + OFF_B0 + o)     = hh;
        *(uint16_t*)(sm + OFF_B0 + o + 8) = hl;
    }
    __syncthreads();

    const int xslot = ((wp << 1) + hi)       * 512 + lane * 16;
    const int pslot = ((wp << 1) + (hi ^ 1)) * 512 + lane * 16;
    float c0s[2] = {0, 0}, c1s[2] = {0, 0}, h1fin[2] = {0, 0};

    #pragma unroll 1
    for (int p = 0; p <= SEQT; p++) {
        const int par = p & 1;
        const unsigned char* B0r = sm + OFF_B0 + par * (NB * S0);
        const unsigned char* B1r = sm + OFF_B1 + par * (NB * S1);
        unsigned char* B0w = sm + OFF_B0 + (par ^ 1) * (NB * S0);
        unsigned char* B1w = sm + OFF_B1 + (par ^ 1) * (NB * S1);

        float xn = 0.0f;
        if (p + 1 < SEQT)
            xn = x[((size_t)(b0 + w) * SEQT + (p + 1)) * 32 + lane];

        // ================= layer 0 : t = p =================
        if (p < SEQT) {
            float C0[2][4] = {{0,0,0,0},{0,0,0,0}};
            #pragma unroll
            for (int kt = 0; kt < 6; kt++) {
                uint4 al = *(const uint4*)(sm + OFF_ALO + w * ALO_W + kt * 512 + lane * 16);
                #pragma unroll
                for (int nt = 0; nt < 2; nt++) {
                    uint4 v = *(const uint4*)(B0r + (8 * nt + g) * S0 + kt * 64 + tq * 16);
                    mma_bf16(C0[nt], A0[kt], v.x, v.y);
                    mma_bf16(C0[nt], A0[kt], v.z, v.w);
                    mma_bf16(C0[nt], (const uint32_t*)&al, v.x, v.y);
                }
            }
            // activate: [nt][2r+d]; r==0 is gate A (tanh iff hi==1)
            float a0v[4], a1v[4];
            #pragma unroll
            for (int r = 0; r < 2; r++)
                #pragma unroll
                for (int d = 0; d < 2; d++) {
                    float v0 = C0[0][2 * r + d] + bias0[r];
                    float v1 = C0[1][2 * r + d] + bias0[r];
                    bool th = (hi == 1) && (r == 0);
                    a0v[2 * r + d] = th ? tanhf_(v0) : sigf(v0);
                    a1v[2 * r + d] = th ? tanhf_(v1) : sigf(v1);
                }
            // export the nt I don't update (nt = hi^1)
            float e0 = hi ? a0v[0] : a1v[0], e1 = hi ? a0v[1] : a1v[1];
            float e2 = hi ? a0v[2] : a1v[2], e3 = hi ? a0v[3] : a1v[3];
            *(float4*)(sm + OFF_X0 + xslot) = make_float4(e0, e1, e2, e3);
            asm volatile("bar.sync %0, 64;" :: "r"(1 + wp) : "memory");
            float4 pq = *(const float4*)(sm + OFF_X0 + pslot);
            float pv[4] = {pq.x, pq.y, pq.z, pq.w};
            float kept[4] = {hi ? a1v[0] : a0v[0], hi ? a1v[1] : a0v[1],
                             hi ? a1v[2] : a0v[2], hi ? a1v[3] : a0v[3]};
            #pragma unroll
            for (int d = 0; d < 2; d++) {
                float ig = hi ? pv[d]       : kept[d];
                float fg = hi ? pv[2 + d]   : kept[2 + d];
                float gg = hi ? kept[d]     : pv[d];
                float og = hi ? kept[2 + d] : pv[2 + d];
                float c = fg * c0s[d] + ig * gg;
                c0s[d] = c;
                float h = og * tanhf_(c);
                int b = hi * 8 + 2 * tq + d;
                uint16_t hh, hl; split_bf16(h, hh, hl);
                int oa = boff(b, 32 + jv, S0);
                *(uint16_t*)(B0w + oa)     = hh;   // layer0 recurrence
                *(uint16_t*)(B0w + oa + 8) = hl;
                int ob = boff(b, jv, S1);
                *(uint16_t*)(B1w + ob)     = hh;   // layer1 input
                *(uint16_t*)(B1w + ob + 8) = hl;
            }
        }

        // ================= layer 1 : t = p-1 =================
        if (p >= 1) {
            float C1[2][4] = {{0,0,0,0},{0,0,0,0}};
            #pragma unroll
            for (int kt = 0; kt < 8; kt++) {
                uint4 al = *(const uint4*)(sm + OFF_ALO + w * ALO_W + (6 + kt) * 512 + lane * 16);
                #pragma unroll
                for (int nt = 0; nt < 2; nt++) {
                    uint4 v = *(const uint4*)(B1r + (8 * nt + g) * S1 + kt * 64 + tq * 16);
                    mma_bf16(C1[nt], A1[kt], v.x, v.y);
                    mma_bf16(C1[nt], A1[kt], v.z, v.w);
                    mma_bf16(C1[nt], (const uint32_t*)&al, v.x, v.y);
                }
            }
            float a0v[4], a1v[4];
            #pragma unroll
            for (int r = 0; r < 2; r++)
                #pragma unroll
                for (int d = 0; d < 2; d++) {
                    float v0 = C1[0][2 * r + d] + bias1[r];
                    float v1 = C1[1][2 * r + d] + bias1[r];
                    bool th = (hi == 1) && (r == 0);
                    a0v[2 * r + d] = th ? tanhf_(v0) : sigf(v0);
                    a1v[2 * r + d] = th ? tanhf_(v1) : sigf(v1);
                }
            float e0 = hi ? a0v[0] : a1v[0], e1 = hi ? a0v[1] : a1v[1];
            float e2 = hi ? a0v[2] : a1v[2], e3 = hi ? a0v[3] : a1v[3];
            *(float4*)(sm + OFF_X1 + xslot) = make_float4(e0, e1, e2, e3);
            asm volatile("bar.sync %0, 64;" :: "r"(1 + wp) : "memory");
            float4 pq = *(const float4*)(sm + OFF_X1 + pslot);
            float pv[4] = {pq.x, pq.y, pq.z, pq.w};
            float kept[4] = {hi ? a1v[0] : a0v[0], hi ? a1v[1] : a0v[1],
                             hi ? a1v[2] : a0v[2], hi ? a1v[3] : a0v[3]};
            #pragma unroll
            for (int d = 0; d < 2; d++) {
                float ig = hi ? pv[d]       : kept[d];
                float fg = hi ? pv[2 + d]   : kept[2 + d];
                float gg = hi ? kept[d]     : pv[d];
                float og = hi ? kept[2 + d] : pv[2 + d];
                float c = fg * c1s[d] + ig * gg;
                c1s[d] = c;
                float h = og * tanhf_(c);
                h1fin[d] = h;
                int b = hi * 8 + 2 * tq + d;
                uint16_t hh, hl; split_bf16(h, hh, hl);
                int oc = boff(b, 64 + jv, S1);
                *(uint16_t*)(B1w + oc)     = hh;   // layer1 recurrence
                *(uint16_t*)(B1w + oc + 8) = hl;
            }
        }

        if (p + 1 < SEQT) {
            uint16_t hh, hl; split_bf16(xn, hh, hl);
            int o = boff(w, lane, S0);
            *(uint16_t*)(B0w + o)     = hh;
            *(uint16_t*)(B0w + o + 8) = hl;
        }
        __syncthreads();
    }

    // ---- LayerNorm + FC on h1(T-1) ----
    float* hb = (float*)(sm + OFF_X0);
    #pragma unroll
    for (int d = 0; d < 2; d++) {
        int b = hi * 8 + 2 * tq + d;
        hb[b * 64 + jv] = h1fin[d];
    }
    __syncthreads();
    if (tid < NB) {
        const float* h = hb + tid * 64;
        float mu = 0.0f;
        #pragma unroll
        for (int j = 0; j < 64; j++) mu += h[j];
        mu *= (1.0f / 64.0f);
        float var = 0.0f;
        #pragma unroll
        for (int j = 0; j < 64; j++) { float dd = h[j] - mu; var += dd * dd; }
        var *= (1.0f / 64.0f);
        float rstd = rsqrtf(var + 1e-5f);
        float s = 0.0f;
        #pragma unroll
        for (int j = 0; j < 64; j++)
            s += ((h[j] - mu) * rstd * ln_g[j] + ln_b[j]) * fc_w[j];
        out[b0 + tid] = s + fc_b[0];
    }
}

extern "C" void kernel_launch(void* const* d_in, const int* in_sizes, int n_in,
                              void* d_out, int out_size)
{
    const float* x     = (const float*)d_in[0];
    const float* W_ih0 = (const float*)d_in[1];
    const float* W_hh0 = (const float*)d_in[2];
    const float* b_ih0 = (const float*)d_in[3];
    const float* b_hh0 = (const float*)d_in[4];
    const float* W_ih1 = (const float*)d_in[5];
    const float* W_hh1 = (const float*)d_in[6];
    const float* b_ih1 = (const float*)d_in[7];
    const float* b_hh1 = (const float*)d_in[8];
    const float* ln_g  = (const float*)d_in[9];
    const float* ln_b  = (const float*)d_in[10];
    const float* fc_w  = (const float*)d_in[11];
    const float* fc_b  = (const float*)d_in[12];
    float* out = (float*)d_out;

    cudaFuncSetAttribute(lstm_fused, cudaFuncAttributeMaxDynamicSharedMemorySize, SMEM_TOTAL);
    lstm_fused<<<2048 / NB, NT, SMEM_TOTAL>>>(x, W_ih0, W_hh0, b_ih0, b_hh0,
                                              W_ih1, W_hh1, b_ih1, b_hh1,
                                              ln_g, ln_b, fc_w, fc_b, out);
}

// round 7
// speedup vs baseline: 3.7109x; 1.0830x over previous
#include <cuda_runtime.h>
#include <cuda_bf16.h>
#include <stdint.h>

#define SEQT 512
#define NB   16
#define NT   512

#define S0   448    // layer0 B row stride (K=96 -> 6x64B groups, padded)
#define S1   576    // layer1 B row stride (K=128 -> 8x64B groups, padded)

// dynamic SMEM map (bytes)
#define OFF_B0   0                         // 2 parities x 16*448 = 14336
#define OFF_B1   14336                     // 2 parities x 16*576 = 18432
#define OFF_X0   32768                     // L0 exchange: 16 slots x 512B
#define OFF_X1   40960                     // L1 exchange
#define OFF_ALO  49152                     // 16 warps x 7168
#define ALO_W    7168
#define SMEM_TOTAL (OFF_ALO + 16 * ALO_W)  // 163840

__device__ __forceinline__ void mma_bf16(float c[4], const uint32_t a[4],
                                         uint32_t b0, uint32_t b1) {
    asm volatile(
        "mma.sync.aligned.m16n8k16.row.col.f32.bf16.bf16.f32 "
        "{%0,%1,%2,%3}, {%4,%5,%6,%7}, {%8,%9}, {%0,%1,%2,%3};"
        : "+f"(c[0]), "+f"(c[1]), "+f"(c[2]), "+f"(c[3])
        : "r"(a[0]), "r"(a[1]), "r"(a[2]), "r"(a[3]), "r"(b0), "r"(b1));
}

__device__ __forceinline__ void split_bf16(float v, uint16_t& hi, uint16_t& lo) {
    __nv_bfloat16 h = __float2bfloat16(v);
    __nv_bfloat16 l = __float2bfloat16(v - __bfloat162float(h));
    hi = __bfloat16_as_ushort(h);
    lo = __bfloat16_as_ushort(l);
}

__device__ __forceinline__ float ex2f(float v) { float r; asm("ex2.approx.f32 %0, %1;" : "=f"(r) : "f"(v)); return r; }
__device__ __forceinline__ float rcpf(float v) { float r; asm("rcp.approx.f32 %0, %1;" : "=f"(r) : "f"(v)); return r; }
__device__ __forceinline__ float sigf(float x)   { return rcpf(1.0f + ex2f(-1.442695041f * x)); }
__device__ __forceinline__ float tanhf_(float x) { return fmaf(2.0f, rcpf(1.0f + ex2f(-2.885390082f * x)), -1.0f); }

// byte offset of (batch n, k) in hi/lo-interleaved B buffer
__device__ __forceinline__ int boff(int n, int k, int S) {
    int r = k & 15;
    return n * S + (k >> 4) * 64 + ((r >> 1) & 3) * 16 + ((r >> 3) << 2) + ((r & 1) << 1);
}

__global__ void __launch_bounds__(NT, 1)
lstm_fused(const float* __restrict__ x,
           const float* __restrict__ W_ih0, const float* __restrict__ W_hh0,
           const float* __restrict__ b_ih0, const float* __restrict__ b_hh0,
           const float* __restrict__ W_ih1, const float* __restrict__ W_hh1,
           const float* __restrict__ b_ih1, const float* __restrict__ b_hh1,
           const float* __restrict__ ln_g, const float* __restrict__ ln_b,
           const float* __restrict__ fc_w, const float* __restrict__ fc_b,
           float* __restrict__ out)
{
    extern __shared__ __align__(16) unsigned char sm[];
    const int tid  = threadIdx.x;
    const int w    = tid >> 5;
    const int lane = tid & 31;
    const int g    = lane >> 2;
    const int tq   = lane & 3;
    const int wp   = w & 7;          // j-block (pair id)
    const int hi   = w >> 3;         // 0: gates {i,f}, 1: gates {g,o}
    const int jv   = 8 * wp + g;     // cell index this thread owns
    const int b0   = blockIdx.x * NB;

    for (int i = tid; i < 32768 / 4; i += NT) ((uint32_t*)sm)[i] = 0;

    // ---- A fragments (gate-pair row order), hi in regs, lo in SMEM ----
    uint32_t A0[6][4], A1[8][4];
    #pragma unroll
    for (int kt = 0; kt < 6; kt++) {
        uint32_t lo4[4];
        #pragma unroll
        for (int i = 0; i < 4; i++) {
            int m = (2 * hi + (i & 1)) * 64 + jv;
            int k = 16 * kt + 2 * tq + (i >> 1) * 8;
            float v0 = (k < 32)     ? W_ih0[m * 32 + k]     : W_hh0[m * 64 + k - 32];
            float v1 = (k + 1 < 32) ? W_ih0[m * 32 + k + 1] : W_hh0[m * 64 + k + 1 - 32];
            uint16_t h0, l0, h1, l1;
            split_bf16(v0, h0, l0); split_bf16(v1, h1, l1);
            A0[kt][i] = (uint32_t)h0 | ((uint32_t)h1 << 16);
            lo4[i]    = (uint32_t)l0 | ((uint32_t)l1 << 16);
        }
        *(uint4*)(sm + OFF_ALO + w * ALO_W + kt * 512 + lane * 16) = *(uint4*)lo4;
    }
    #pragma unroll
    for (int kt = 0; kt < 8; kt++) {
        uint32_t lo4[4];
        #pragma unroll
        for (int i = 0; i < 4; i++) {
            int m = (2 * hi + (i & 1)) * 64 + jv;
            int k = 16 * kt + 2 * tq + (i >> 1) * 8;
            float v0 = (k < 64)     ? W_ih1[m * 64 + k]     : W_hh1[m * 64 + k - 64];
            float v1 = (k + 1 < 64) ? W_ih1[m * 64 + k + 1] : W_hh1[m * 64 + k + 1 - 64];
            uint16_t h0, l0, h1, l1;
            split_bf16(v0, h0, l0); split_bf16(v1, h1, l1);
            A1[kt][i] = (uint32_t)h0 | ((uint32_t)h1 << 16);
            lo4[i]    = (uint32_t)l0 | ((uint32_t)l1 << 16);
        }
        *(uint4*)(sm + OFF_ALO + w * ALO_W + (6 + kt) * 512 + lane * 16) = *(uint4*)lo4;
    }

    float bias0[2], bias1[2];
    #pragma unroll
    for (int r = 0; r < 2; r++) {
        int m = (2 * hi + r) * 64 + jv;
        bias0[r] = b_ih0[m] + b_hh0[m];
        bias1[r] = b_ih1[m] + b_hh1[m];
    }

    // x(0) -> B0 parity 0
    {
        float xv = x[((size_t)(b0 + w) * SEQT) * 32 + lane];
        uint16_t hh, hl; split_bf16(xv, hh, hl);
        int o = boff(w, lane, S0);
        *(uint16_t*)(sm + OFF_B0 + o)     = hh;
        *(uint16_t*)(sm + OFF_B0 + o + 8) = hl;
    }
    __syncthreads();

    const int xslot = ((wp << 1) + hi)       * 512 + lane * 16;
    const int pslot = ((wp << 1) + (hi ^ 1)) * 512 + lane * 16;
    float c0s[2] = {0, 0}, c1s[2] = {0, 0}, h1fin[2] = {0, 0};

    #pragma unroll 1
    for (int p = 0; p <= SEQT; p++) {
        const int par = p & 1;
        const unsigned char* B0r = sm + OFF_B0 + par * (NB * S0);
        const unsigned char* B1r = sm + OFF_B1 + par * (NB * S1);
        unsigned char* B0w = sm + OFF_B0 + (par ^ 1) * (NB * S0);
        unsigned char* B1w = sm + OFF_B1 + (par ^ 1) * (NB * S1);

        float xn = 0.0f;
        if (p + 1 < SEQT)
            xn = x[((size_t)(b0 + w) * SEQT + (p + 1)) * 32 + lane];

        // ================= MMA phase: both layers back-to-back =================
        float C0[2][4] = {{0,0,0,0},{0,0,0,0}};
        float C1[2][4] = {{0,0,0,0},{0,0,0,0}};

        if (p < SEQT) {
            #pragma unroll
            for (int kt = 0; kt < 6; kt++) {
                uint4 al = *(const uint4*)(sm + OFF_ALO + w * ALO_W + kt * 512 + lane * 16);
                #pragma unroll
                for (int nt = 0; nt < 2; nt++) {
                    uint4 v = *(const uint4*)(B0r + (8 * nt + g) * S0 + kt * 64 + tq * 16);
                    mma_bf16(C0[nt], A0[kt], v.x, v.y);
                    mma_bf16(C0[nt], A0[kt], v.z, v.w);
                    mma_bf16(C0[nt], (const uint32_t*)&al, v.x, v.y);
                }
            }
        }
        if (p >= 1) {
            #pragma unroll
            for (int kt = 0; kt < 8; kt++) {
                uint4 al = *(const uint4*)(sm + OFF_ALO + w * ALO_W + (6 + kt) * 512 + lane * 16);
                #pragma unroll
                for (int nt = 0; nt < 2; nt++) {
                    uint4 v = *(const uint4*)(B1r + (8 * nt + g) * S1 + kt * 64 + tq * 16);
                    mma_bf16(C1[nt], A1[kt], v.x, v.y);
                    mma_bf16(C1[nt], A1[kt], v.z, v.w);
                    mma_bf16(C1[nt], (const uint32_t*)&al, v.x, v.y);
                }
            }
        }

        // ================= activations for both layers, then ONE pair barrier ====
        float k0[4], p0e[4], k1[4], p1e[4];   // kept / exported (L0, L1)
        if (p < SEQT) {
            #pragma unroll
            for (int r = 0; r < 2; r++)
                #pragma unroll
                for (int d = 0; d < 2; d++) {
                    float v0 = C0[0][2 * r + d] + bias0[r];
                    float v1 = C0[1][2 * r + d] + bias0[r];
                    bool th = (hi == 1) && (r == 0);
                    float a0 = th ? tanhf_(v0) : sigf(v0);
                    float a1 = th ? tanhf_(v1) : sigf(v1);
                    k0[2 * r + d]  = hi ? a1 : a0;
                    p0e[2 * r + d] = hi ? a0 : a1;
                }
            *(float4*)(sm + OFF_X0 + xslot) = make_float4(p0e[0], p0e[1], p0e[2], p0e[3]);
        }
        if (p >= 1) {
            #pragma unroll
            for (int r = 0; r < 2; r++)
                #pragma unroll
                for (int d = 0; d < 2; d++) {
                    float v0 = C1[0][2 * r + d] + bias1[r];
                    float v1 = C1[1][2 * r + d] + bias1[r];
                    bool th = (hi == 1) && (r == 0);
                    float a0 = th ? tanhf_(v0) : sigf(v0);
                    float a1 = th ? tanhf_(v1) : sigf(v1);
                    k1[2 * r + d]  = hi ? a1 : a0;
                    p1e[2 * r + d] = hi ? a0 : a1;
                }
            *(float4*)(sm + OFF_X1 + xslot) = make_float4(p1e[0], p1e[1], p1e[2], p1e[3]);
        }
        asm volatile("bar.sync %0, 64;" :: "r"(1 + wp) : "memory");

        // ================= updates for both layers =================
        if (p < SEQT) {
            float4 pq = *(const float4*)(sm + OFF_X0 + pslot);
            float pv[4] = {pq.x, pq.y, pq.z, pq.w};
            #pragma unroll
            for (int d = 0; d < 2; d++) {
                float ig = hi ? pv[d]       : k0[d];
                float fg = hi ? pv[2 + d]   : k0[2 + d];
                float gg = hi ? k0[d]       : pv[d];
                float og = hi ? k0[2 + d]   : pv[2 + d];
                float c = fg * c0s[d] + ig * gg;
                c0s[d] = c;
                float h = og * tanhf_(c);
                int b = hi * 8 + 2 * tq + d;
                uint16_t hh, hl; split_bf16(h, hh, hl);
                int oa = boff(b, 32 + jv, S0);
                *(uint16_t*)(B0w + oa)     = hh;
                *(uint16_t*)(B0w + oa + 8) = hl;
                int ob = boff(b, jv, S1);
                *(uint16_t*)(B1w + ob)     = hh;
                *(uint16_t*)(B1w + ob + 8) = hl;
            }
        }
        if (p >= 1) {
            float4 pq = *(const float4*)(sm + OFF_X1 + pslot);
            float pv[4] = {pq.x, pq.y, pq.z, pq.w};
            #pragma unroll
            for (int d = 0; d < 2; d++) {
                float ig = hi ? pv[d]       : k1[d];
                float fg = hi ? pv[2 + d]   : k1[2 + d];
                float gg = hi ? k1[d]       : pv[d];
                float og = hi ? k1[2 + d]   : pv[2 + d];
                float c = fg * c1s[d] + ig * gg;
                c1s[d] = c;
                float h = og * tanhf_(c);
                h1fin[d] = h;
                int b = hi * 8 + 2 * tq + d;
                uint16_t hh, hl; split_bf16(h, hh, hl);
                int oc = boff(b, 64 + jv, S1);
                *(uint16_t*)(B1w + oc)     = hh;
                *(uint16_t*)(B1w + oc + 8) = hl;
            }
        }

        if (p + 1 < SEQT) {
            uint16_t hh, hl; split_bf16(xn, hh, hl);
            int o = boff(w, lane, S0);
            *(uint16_t*)(B0w + o)     = hh;
            *(uint16_t*)(B0w + o + 8) = hl;
        }
        __syncthreads();
    }

    // ---- LayerNorm + FC on h1(T-1) ----
    float* hb = (float*)(sm + OFF_X0);
    #pragma unroll
    for (int d = 0; d < 2; d++) {
        int b = hi * 8 + 2 * tq + d;
        hb[b * 64 + jv] = h1fin[d];
    }
    __syncthreads();
    if (tid < NB) {
        const float* h = hb + tid * 64;
        float mu = 0.0f;
        #pragma unroll
        for (int j = 0; j < 64; j++) mu += h[j];
        mu *= (1.0f / 64.0f);
        float var = 0.0f;
        #pragma unroll
        for (int j = 0; j < 64; j++) { float dd = h[j] - mu; var += dd * dd; }
        var *= (1.0f / 64.0f);
        float rstd = rsqrtf(var + 1e-5f);
        float s = 0.0f;
        #pragma unroll
        for (int j = 0; j < 64; j++)
            s += ((h[j] - mu) * rstd * ln_g[j] + ln_b[j]) * fc_w[j];
        out[b0 + tid] = s + fc_b[0];
    }
}

extern "C" void kernel_launch(void* const* d_in, const int* in_sizes, int n_in,
                              void* d_out, int out_size)
{
    const float* x     = (const float*)d_in[0];
    const float* W_ih0 = (const float*)d_in[1];
    const float* W_hh0 = (const float*)d_in[2];
    const float* b_ih0 = (const float*)d_in[3];
    const float* b_hh0 = (const float*)d_in[4];
    const float* W_ih1 = (const float*)d_in[5];
    const float* W_hh1 = (const float*)d_in[6];
    const float* b_ih1 = (const float*)d_in[7];
    const float* b_hh1 = (const float*)d_in[8];
    const float* ln_g  = (const float*)d_in[9];
    const float* ln_b  = (const float*)d_in[10];
    const float* fc_w  = (const float*)d_in[11];
    const float* fc_b  = (const float*)d_in[12];
    float* out = (float*)d_out;

    cudaFuncSetAttribute(lstm_fused, cudaFuncAttributeMaxDynamicSharedMemorySize, SMEM_TOTAL);
    lstm_fused<<<2048 / NB, NT, SMEM_TOTAL>>>(x, W_ih0, W_hh0, b_ih0, b_hh0,
                                              W_ih1, W_hh1, b_ih1, b_hh1,
                                              ln_g, ln_b, fc_w, fc_b, out);
}